// round 13
// baseline (speedup 1.0000x reference)
#include <cuda_runtime.h>
#include <stdint.h>

#define NB 8
#define NANCH 13343
#define TOPK 1000
#define CAND 2048
#define NCLS 80
#define BPB 36                 // blocks per batch
#define NBLK (BPB * NB)        // 288 total blocks (<=296 guaranteed wave-1 resident at occ 2)

// ---------------- scratch (device globals; no allocation allowed) ----------------
__device__ unsigned long long g_key[NB * NANCH];   // score<<34 | (16383-a)<<7 | cls
__device__ unsigned           g_sbits[NB * NANCH];
__device__ float4             g_box4[NB * NANCH];

__device__ unsigned long long g_cand[NB * CAND];
__device__ int                g_ncand[NB];
__device__ unsigned           g_maxc_u[NB];

__device__ float    g_tsc[NB * 1024];
__device__ int      g_tcl[NB * 1024];
__device__ float4   g_tbox[NB * 1024];

__device__ unsigned      g_mask[NB * TOPK * 32];   // zero-init; triangular-skipped words stay 0
__device__ unsigned char g_rnz[NB * TOPK];

__device__ int           bar_cnt[NB];              // self-resetting arrival counters
__device__ volatile int  bar_gen[NB];              // generation (monotone across replays)

struct Ptrs {
    const float* cls[5];
    const float* cnt[5];
    const float* reg[5];
};

__device__ __forceinline__ unsigned enc_f(float f) {
    unsigned b = __float_as_uint(f);
    return (b & 0x80000000u) ? ~b : (b | 0x80000000u);
}
__device__ __forceinline__ float dec_f(unsigned u) {
    unsigned b = (u & 0x80000000u) ? (u ^ 0x80000000u) : ~u;
    return __uint_as_float(b);
}

// ---------------- XLA-compatible sigmoid (fma-free Horner, verified passing) ----------------
__device__ __forceinline__ float xla_tanh(float x) {
    float xc = fminf(fmaxf(x, -7.90531110763549805f), 7.90531110763549805f);
    float x2 = __fmul_rn(xc, xc);
    float p = -2.76076847742355e-16f;
    p = __fadd_rn(__fmul_rn(p, x2), 2.00018790482477e-13f);
    p = __fadd_rn(__fmul_rn(p, x2), -8.60467152213735e-11f);
    p = __fadd_rn(__fmul_rn(p, x2), 5.12229709037114e-08f);
    p = __fadd_rn(__fmul_rn(p, x2), 1.48572235717979e-05f);
    p = __fadd_rn(__fmul_rn(p, x2), 6.37261928875436e-04f);
    p = __fadd_rn(__fmul_rn(p, x2), 4.89352455891786e-03f);
    p = __fmul_rn(xc, p);
    float q = 1.19825839466702e-06f;
    q = __fadd_rn(__fmul_rn(q, x2), 1.18534705686654e-04f);
    q = __fadd_rn(__fmul_rn(q, x2), 2.26843463243900e-03f);
    q = __fadd_rn(__fmul_rn(q, x2), 4.89352518554385e-03f);
    float r = __fdiv_rn(p, q);
    return (fabsf(x) < 0.0004f) ? x : r;
}
__device__ __forceinline__ float xla_sigmoid(float x) {
    return __fadd_rn(0.5f, __fmul_rn(0.5f, xla_tanh(__fmul_rn(0.5f, x))));
}

// ---------------- per-batch device barrier (sense-reversing, replay-safe) ----------------
// block bar.sync orders all block threads' prior global writes before tid0's
// release fence (grid_group::sync pattern, proven in r8). Spin is bounded so a
// residency surprise fails rel-err instead of hanging the harness.
__device__ __forceinline__ void batch_barrier(int b) {
    __syncthreads();
    if (threadIdx.x == 0) {
        __threadfence();                       // release this block's writes
        int g = bar_gen[b];
        if (atomicAdd(&bar_cnt[b], 1) == BPB - 1) {
            bar_cnt[b] = 0;                    // reset BEFORE generation bump
            __threadfence();
            bar_gen[b] = g + 1;
        } else {
            unsigned spins = 0;
            while (bar_gen[b] == g && spins < 0x20000000u) spins++;
        }
        __threadfence();                       // acquire peers' writes
    }
    __syncthreads();
}

// ---------------- the whole pipeline in ONE kernel ----------------
__global__ __launch_bounds__(1024, 2) void k_all(Ptrs P, float* out) {
    __shared__ union {
        struct { unsigned hist[1024]; unsigned wsum[32]; } sel;
        unsigned long long skey[CAND];
        struct { float sx1[TOPK], sy1[TOPK], sx2[TOPK], sy2[TOPK], sar[TOPK]; } msk;
    } sm;
    __shared__ unsigned s_B, s_above, s_cnt;
    __shared__ unsigned s_valid[32], s_ne[32];
    __shared__ volatile unsigned s_removed[32];

    int blk = blockIdx.x;
    int b   = blk & 7;     // batch
    int bl  = blk >> 3;    // 0..35 within batch
    int tid = threadIdx.x;
    int lane = tid & 31, wrp = tid >> 5;
    float ninf = -__int_as_float(0x7f800000);

    // ================= stage 1: score =================
    {
        int a = bl * 1024 + tid;
        if (a < NANCH) {
            int l, p;
            if (a < 10000)      { l = 0; p = a; }
            else if (a < 12500) { l = 1; p = a - 10000; }
            else if (a < 13125) { l = 2; p = a - 12500; }
            else if (a < 13294) { l = 3; p = a - 13125; }
            else                { l = 4; p = a - 13294; }

            const int wlv[5] = {100, 50, 25, 13, 7};
            const int hwv[5] = {10000, 2500, 625, 169, 49};
            const int stv[5] = {8, 16, 32, 64, 128};
            int w = wlv[l], HW = hwv[l], s = stv[l];
            int y = p / w, x = p - y * w;
            float cx = (float)(x * s + (s >> 1));
            float cy = (float)(y * s + (s >> 1));

            const float* cp = P.cls[l] + (size_t)b * NCLS * HW + p;
            float m1 = ninf, m2 = ninf;
            int i1 = 0, i2 = 0;
#pragma unroll 8
            for (int c = 0; c < NCLS; c++) {
                float v = __ldg(cp + (size_t)c * HW);
                if (v > m1) { m2 = m1; i2 = i1; m1 = v; i1 = c; }
                else if (v > m2) { m2 = v; i2 = c; }
            }
            float s1 = xla_sigmoid(m1);
            float s2 = xla_sigmoid(m2);
            float best = s1;
            int bi = i1;
            if (s2 > s1 || (s2 == s1 && i2 < i1)) { best = fmaxf(s1, s2); bi = i2; }
            float cv = xla_sigmoid(__ldg(P.cnt[l] + (size_t)b * HW + p));
            float score = sqrtf(__fmul_rn(best, cv));

            int o = b * NANCH + a;
            unsigned sbits = __float_as_uint(score);
            g_sbits[o] = sbits;
            g_key[o] = ((unsigned long long)sbits << 34)
                     | ((unsigned long long)(16383 - a) << 7)
                     | (unsigned long long)(bi + 1);

            const float* reg = P.reg[l];
            float r0 = __ldg(reg + ((size_t)b * 4 + 0) * HW + p);
            float r1 = __ldg(reg + ((size_t)b * 4 + 1) * HW + p);
            float r2 = __ldg(reg + ((size_t)b * 4 + 2) * HW + p);
            float r3 = __ldg(reg + ((size_t)b * 4 + 3) * HW + p);
            g_box4[o] = make_float4(__fsub_rn(cx, r0), __fsub_rn(cy, r1),
                                    __fadd_rn(cx, r2), __fadd_rn(cy, r3));
        }
    }
    batch_barrier(b);

    // ================= stage 2: radix select (leader block only) =================
    if (bl == 0) {
        const unsigned* sb = g_sbits + b * NANCH;
        const unsigned long long* kb = g_key + b * NANCH;
        if (tid == 0) g_maxc_u[b] = enc_f(ninf);

        unsigned vv[14];
#pragma unroll
        for (int r = 0; r < 14; r++) {
            int i = tid + r * 1024;
            vv[r] = (i < NANCH) ? sb[i] : 0xFFFFFFFFu;
        }

        unsigned prefix = 0;
        unsigned target = TOPK;
        for (int pass = 0; pass < 3; pass++) {
            int shift = 20 - 10 * pass;
            sm.sel.hist[tid] = 0;
            __syncthreads();
#pragma unroll
            for (int r = 0; r < 14; r++) {
                unsigned v = vv[r];
                if (v != 0xFFFFFFFFu) {
                    bool in = (pass == 0) || ((v >> (shift + 10)) == prefix);
                    if (in) atomicAdd(&sm.sel.hist[(v >> shift) & 1023], 1u);
                }
            }
            __syncthreads();
            unsigned h = sm.sel.hist[tid];
            unsigned v = h;
#pragma unroll
            for (int off = 1; off < 32; off <<= 1) {
                unsigned u = __shfl_down_sync(0xffffffffu, v, off);
                if (lane + off < 32) v += u;
            }
            if (lane == 0) sm.sel.wsum[wrp] = v;
            __syncthreads();
            if (tid < 32) {
                unsigned wv = sm.sel.wsum[tid];
                unsigned acc = wv;
#pragma unroll
                for (int off = 1; off < 32; off <<= 1) {
                    unsigned u = __shfl_down_sync(0xffffffffu, acc, off);
                    if (tid + off < 32) acc += u;
                }
                sm.sel.wsum[tid] = acc - wv;
            }
            __syncthreads();
            unsigned S = v + sm.sel.wsum[wrp];
            unsigned nxt = S - h;
            if (S >= target && nxt < target) { s_B = tid; s_above = nxt; }
            __syncthreads();
            prefix = (prefix << 10) | s_B;
            target = target - s_above;
            __syncthreads();
        }
        unsigned T = prefix;

        if (tid == 0) s_cnt = 0;
        __syncthreads();
#pragma unroll
        for (int r = 0; r < 14; r++) {
            int i = tid + r * 1024;
            if (i < NANCH && vv[r] >= T && vv[r] != 0xFFFFFFFFu) {
                unsigned pos = atomicAdd(&s_cnt, 1u);
                if (pos < CAND) g_cand[b * CAND + pos] = kb[i];
            }
        }
        __syncthreads();
        if (tid == 0) g_ncand[b] = (int)min(s_cnt, (unsigned)CAND);
    }
    batch_barrier(b);

    // ================= stage 3: rank-by-count + gather (16 blocks, 128 threads each) =================
    if (bl < 16) {
        int n = g_ncand[b];
        int n4 = (n + 3) & ~3;
        for (int i = tid; i < n4; i += 1024)
            sm.skey[i] = (i < n) ? g_cand[b * CAND + i] : 0ULL;
        __syncthreads();

        unsigned mu = 0;
        if (tid < 128) {
            int c = bl * 128 + tid;
            if (c < n) {
                unsigned long long k = sm.skey[c];
                int cnt = 0;
                for (int j = 0; j < n4; j += 4) {
                    cnt += (int)(sm.skey[j]     > k) + (int)(sm.skey[j + 1] > k)
                         + (int)(sm.skey[j + 2] > k) + (int)(sm.skey[j + 3] > k);
                }
                if (cnt < TOPK) {
                    unsigned sbits = (unsigned)(k >> 34);
                    int a = 16383 - (int)((k >> 7) & 16383);
                    int cl = (int)(k & 127);
                    float sc = __uint_as_float(sbits);
                    float4 bx = g_box4[b * NANCH + a];
                    int to = b * 1024 + cnt;
                    g_tsc[to] = sc;
                    g_tcl[to] = cl;
                    g_tbox[to] = bx;
                    bool valid = (sc >= 0.05f);
                    float m = valid ? fmaxf(fmaxf(bx.x, bx.y), fmaxf(bx.z, bx.w)) : 0.0f;
                    mu = enc_f(m);
                }
            }
        }
#pragma unroll
        for (int o = 16; o > 0; o >>= 1) mu = max(mu, __shfl_down_sync(0xffffffffu, mu, o));
        if (lane == 0 && wrp < 4 && mu != 0) atomicMax(&g_maxc_u[b], mu);
    }
    batch_barrier(b);

    // ================= stage 4: suppression bitmask =================
    // block bl handles rows [bl*32, bl*32+32): one row per warp; i>>5 == bl,
    // so only boxes j >= bl*32 are needed (triangular skip).
    if (bl * 32 < TOPK) {
        int base = b * 1024;
        float maxc = dec_f(g_maxc_u[b]);
        int jstart = bl * 32;
        {
            int idx = jstart + tid;
            if (idx < TOPK) {
                float4 bx = g_tbox[base + idx];
                float off = __fmul_rn((float)g_tcl[base + idx], __fadd_rn(maxc, 1.0f));
                float ox1 = __fadd_rn(bx.x, off);
                float oy1 = __fadd_rn(bx.y, off);
                float ox2 = __fadd_rn(bx.z, off);
                float oy2 = __fadd_rn(bx.w, off);
                sm.msk.sx1[idx] = ox1; sm.msk.sy1[idx] = oy1;
                sm.msk.sx2[idx] = ox2; sm.msk.sy2[idx] = oy2;
                sm.msk.sar[idx] = __fmul_rn(__fadd_rn(__fsub_rn(ox2, ox1), 1.0f),
                                            __fadd_rn(__fsub_rn(oy2, oy1), 1.0f));
            }
        }
        __syncthreads();

        int i = bl * 32 + wrp;
        if (i < TOPK) {
            float x1i = sm.msk.sx1[i], y1i = sm.msk.sy1[i];
            float x2i = sm.msk.sx2[i], y2i = sm.msk.sy2[i];
            float ai  = sm.msk.sar[i];
            unsigned* mrowp = g_mask + ((size_t)(b * TOPK + i)) * 32;

            unsigned rowor = 0;
#pragma unroll 4
            for (int w = bl; w < 32; w++) {
                int j = w * 32 + lane;
                unsigned bit = 0;
                if (j > i && j < TOPK) {
                    float xx1 = fmaxf(x1i, sm.msk.sx1[j]);
                    float yy1 = fmaxf(y1i, sm.msk.sy1[j]);
                    float xx2 = fminf(x2i, sm.msk.sx2[j]);
                    float yy2 = fminf(y2i, sm.msk.sy2[j]);
                    float iw = fmaxf(__fsub_rn(xx2, xx1), 0.0f);
                    float ih = fmaxf(__fsub_rn(yy2, yy1), 0.0f);
                    float inter = __fmul_rn(iw, ih);
                    // inter==0 -> iou in {0,-0,NaN}, never > 0.6: skip divide exactly.
                    if (inter > 0.0f) {
                        float uni = __fsub_rn(__fadd_rn(ai, sm.msk.sar[j]), inter);
                        float iou = __fdiv_rn(inter, uni);
                        bit = (iou > 0.6f) ? 1u : 0u;
                    }
                }
                unsigned word = __ballot_sync(0xffffffffu, bit);
                if (lane == 0) {
                    mrowp[w] = word;
                    rowor |= word;
                }
            }
            if (lane == 0) g_rnz[b * TOPK + i] = (rowor != 0) ? 1 : 0;
        }
    }
    batch_barrier(b);

    // ================= stage 5: greedy scan + output (leader block only) =================
    if (bl != 0) return;
    {
        int base = b * 1024;
        {
            int t = tid;
            int v = 0, nz = 0;
            if (t < TOPK) {
                v = (g_tsc[base + t] >= 0.05f) ? 1 : 0;
                nz = g_rnz[b * TOPK + t];
            }
            unsigned bv = __ballot_sync(0xffffffffu, v);
            unsigned bn = __ballot_sync(0xffffffffu, nz);
            if (lane == 0 && t < TOPK) { s_valid[t >> 5] = bv; s_ne[t >> 5] = bn; }
        }
        if (tid < 32) s_removed[tid] = 0;
        __syncthreads();

        if (tid < 32) {
            for (int w = 0; w < 32; ++w) {
                unsigned cand = s_valid[w] & s_ne[w];
                while (true) {
                    unsigned rm = s_removed[w];
                    unsigned act = cand & ~rm;
                    if (!act) break;
                    int bp = __ffs(act) - 1;
                    cand &= ~(1u << bp);
                    int i = w * 32 + bp;
                    unsigned mrow = g_mask[((size_t)(b * TOPK + i)) * 32 + lane];
                    s_removed[lane] = s_removed[lane] | mrow;
                    __syncwarp();
                }
            }
        }
        __syncthreads();

        float4* boxout = (float4*)(out + (size_t)2 * NB * TOPK);
        int t = tid;
        if (t < TOPK) {
            unsigned rem = s_removed[t >> 5];
            bool keep = (((s_valid[t >> 5] >> (t & 31)) & 1u) != 0u) &&
                        (((rem >> (t & 31)) & 1u) == 0u);
            int to = base + t;
            out[b * TOPK + t] = keep ? g_tsc[to] : 0.0f;
            out[NB * TOPK + b * TOPK + t] = keep ? (float)g_tcl[to] : 0.0f;
            float4 bx = g_tbox[to];
            if (!keep) bx = make_float4(0.f, 0.f, 0.f, 0.f);
            boxout[b * TOPK + t] = bx;
        }
    }
}

// ---------------- launch: one kernel, zero gaps ----------------
extern "C" void kernel_launch(void* const* d_in, const int* in_sizes, int n_in,
                              void* d_out, int out_size) {
    (void)in_sizes; (void)n_in; (void)out_size;
    Ptrs P;
    for (int i = 0; i < 5; i++) {
        P.cls[i] = (const float*)d_in[i];
        P.cnt[i] = (const float*)d_in[5 + i];
        P.reg[i] = (const float*)d_in[10 + i];
    }
    k_all<<<NBLK, 1024>>>(P, (float*)d_out);
}

// round 14
// speedup vs baseline: 1.0259x; 1.0259x over previous
#include <cuda_runtime.h>
#include <stdint.h>

#define NB 8
#define NANCH 13343
#define TOPK 1000
#define CAND 2048
#define NCLS 80
#define BPB 36                 // blocks per batch
#define NBLK (BPB * NB)        // 288 blocks total (<=296 wave-1 resident at occ 2)

// ---------------- scratch (device globals; no allocation allowed) ----------------
__device__ unsigned long long g_key[NB * NANCH];   // score<<34 | (16383-a)<<7 | cls
__device__ unsigned           g_sbits[NB * NANCH];
__device__ float4             g_box4[NB * NANCH];

__device__ unsigned long long g_cand[NB * CAND];
__device__ int                g_ncand[NB];
__device__ unsigned           g_maxc_u[NB];

__device__ float    g_tsc[NB * 1024];
__device__ int      g_tcl[NB * 1024];
__device__ float4   g_tbox[NB * 1024];

__device__ unsigned      g_mask[NB * TOPK * 32];   // zero-init; triangular-skipped words stay 0
__device__ unsigned char g_rnz[NB * TOPK];

__device__ int           bar_cnt[NB];              // per-batch barrier counters (self-reset)
__device__ volatile int  bar_gen[NB];
__device__ int           gbar_cnt;                 // global barrier counter (self-reset)
__device__ volatile int  gbar_gen;

struct Ptrs {
    const float* cls[5];
    const float* cnt[5];
    const float* reg[5];
};

__device__ __forceinline__ unsigned enc_f(float f) {
    unsigned b = __float_as_uint(f);
    return (b & 0x80000000u) ? ~b : (b | 0x80000000u);
}
__device__ __forceinline__ float dec_f(unsigned u) {
    unsigned b = (u & 0x80000000u) ? (u ^ 0x80000000u) : ~u;
    return __uint_as_float(b);
}

// ---------------- XLA-compatible sigmoid (fma-free Horner, verified passing) ----------------
__device__ __forceinline__ float xla_tanh(float x) {
    float xc = fminf(fmaxf(x, -7.90531110763549805f), 7.90531110763549805f);
    float x2 = __fmul_rn(xc, xc);
    float p = -2.76076847742355e-16f;
    p = __fadd_rn(__fmul_rn(p, x2), 2.00018790482477e-13f);
    p = __fadd_rn(__fmul_rn(p, x2), -8.60467152213735e-11f);
    p = __fadd_rn(__fmul_rn(p, x2), 5.12229709037114e-08f);
    p = __fadd_rn(__fmul_rn(p, x2), 1.48572235717979e-05f);
    p = __fadd_rn(__fmul_rn(p, x2), 6.37261928875436e-04f);
    p = __fadd_rn(__fmul_rn(p, x2), 4.89352455891786e-03f);
    p = __fmul_rn(xc, p);
    float q = 1.19825839466702e-06f;
    q = __fadd_rn(__fmul_rn(q, x2), 1.18534705686654e-04f);
    q = __fadd_rn(__fmul_rn(q, x2), 2.26843463243900e-03f);
    q = __fadd_rn(__fmul_rn(q, x2), 4.89352518554385e-03f);
    float r = __fdiv_rn(p, q);
    return (fabsf(x) < 0.0004f) ? x : r;
}
__device__ __forceinline__ float xla_sigmoid(float x) {
    return __fadd_rn(0.5f, __fmul_rn(0.5f, xla_tanh(__fmul_rn(0.5f, x))));
}

// ---------------- barriers (sense-reversing, replay-safe, bounded spin) ----------------
__device__ __forceinline__ void batch_barrier(int b) {
    __syncthreads();
    if (threadIdx.x == 0) {
        __threadfence();
        int g = bar_gen[b];
        if (atomicAdd(&bar_cnt[b], 1) == BPB - 1) {
            bar_cnt[b] = 0;
            __threadfence();
            bar_gen[b] = g + 1;
        } else {
            unsigned spins = 0;
            while (bar_gen[b] == g && spins < 0x20000000u) spins++;
        }
        __threadfence();
    }
    __syncthreads();
}

__device__ __forceinline__ void global_barrier() {
    __syncthreads();
    if (threadIdx.x == 0) {
        __threadfence();
        int g = gbar_gen;
        if (atomicAdd(&gbar_cnt, 1) == NBLK - 1) {
            gbar_cnt = 0;
            __threadfence();
            gbar_gen = g + 1;
        } else {
            unsigned spins = 0;
            while (gbar_gen == g && spins < 0x20000000u) spins++;
        }
        __threadfence();
    }
    __syncthreads();
}

// ---------------- the whole pipeline in ONE kernel ----------------
__global__ __launch_bounds__(1024, 2) void k_all(Ptrs P, float* out) {
    __shared__ union {
        struct { unsigned hist[1024]; unsigned wsum[32]; } sel;
        unsigned long long skey[CAND];
        struct { float sx1[TOPK], sy1[TOPK], sx2[TOPK], sy2[TOPK], sar[TOPK]; } msk;
    } sm;
    __shared__ unsigned s_B, s_above, s_cnt;
    __shared__ unsigned s_valid[32], s_ne[32];
    __shared__ volatile unsigned s_removed[32];

    int blk = blockIdx.x;
    int b   = blk & 7;     // batch this block serves in stages 2-5
    int bl  = blk >> 3;    // 0..35 within batch
    int tid = threadIdx.x;
    int lane = tid & 31, wrp = tid >> 5;
    float ninf = -__int_as_float(0x7f800000);

    // ================= stage 1: score — GLOBAL work distribution (all 288 blocks) =================
    {
        int t = blk * 1024 + tid;      // r6 mapping: coalesced, every SM engaged
        if (t < NB * NANCH) {
            int sb = t / NANCH;
            int a = t - sb * NANCH;

            int l, p;
            if (a < 10000)      { l = 0; p = a; }
            else if (a < 12500) { l = 1; p = a - 10000; }
            else if (a < 13125) { l = 2; p = a - 12500; }
            else if (a < 13294) { l = 3; p = a - 13125; }
            else                { l = 4; p = a - 13294; }

            const int wlv[5] = {100, 50, 25, 13, 7};
            const int hwv[5] = {10000, 2500, 625, 169, 49};
            const int stv[5] = {8, 16, 32, 64, 128};
            int w = wlv[l], HW = hwv[l], s = stv[l];
            int y = p / w, x = p - y * w;
            float cx = (float)(x * s + (s >> 1));
            float cy = (float)(y * s + (s >> 1));

            const float* cp = P.cls[l] + (size_t)sb * NCLS * HW + p;
            float m1 = ninf, m2 = ninf;
            int i1 = 0, i2 = 0;
#pragma unroll 8
            for (int c = 0; c < NCLS; c++) {
                float v = __ldg(cp + (size_t)c * HW);
                if (v > m1) { m2 = m1; i2 = i1; m1 = v; i1 = c; }
                else if (v > m2) { m2 = v; i2 = c; }
            }
            float s1 = xla_sigmoid(m1);
            float s2 = xla_sigmoid(m2);
            float best = s1;
            int bi = i1;
            if (s2 > s1 || (s2 == s1 && i2 < i1)) { best = fmaxf(s1, s2); bi = i2; }
            float cv = xla_sigmoid(__ldg(P.cnt[l] + (size_t)sb * HW + p));
            float score = sqrtf(__fmul_rn(best, cv));

            int o = sb * NANCH + a;
            unsigned sbits = __float_as_uint(score);
            g_sbits[o] = sbits;
            g_key[o] = ((unsigned long long)sbits << 34)
                     | ((unsigned long long)(16383 - a) << 7)
                     | (unsigned long long)(bi + 1);

            const float* reg = P.reg[l];
            float r0 = __ldg(reg + ((size_t)sb * 4 + 0) * HW + p);
            float r1 = __ldg(reg + ((size_t)sb * 4 + 1) * HW + p);
            float r2 = __ldg(reg + ((size_t)sb * 4 + 2) * HW + p);
            float r3 = __ldg(reg + ((size_t)sb * 4 + 3) * HW + p);
            g_box4[o] = make_float4(__fsub_rn(cx, r0), __fsub_rn(cy, r1),
                                    __fadd_rn(cx, r2), __fadd_rn(cy, r3));
        }
    }
    global_barrier();   // score crosses batch partitions -> all blocks sync once

    // ================= stage 2: radix select (leader block per batch) =================
    if (bl == 0) {
        const unsigned* sb = g_sbits + b * NANCH;
        const unsigned long long* kb = g_key + b * NANCH;
        if (tid == 0) g_maxc_u[b] = enc_f(ninf);

        unsigned vv[14];
#pragma unroll
        for (int r = 0; r < 14; r++) {
            int i = tid + r * 1024;
            vv[r] = (i < NANCH) ? sb[i] : 0xFFFFFFFFu;
        }

        unsigned prefix = 0;
        unsigned target = TOPK;
        for (int pass = 0; pass < 3; pass++) {
            int shift = 20 - 10 * pass;
            sm.sel.hist[tid] = 0;
            __syncthreads();
#pragma unroll
            for (int r = 0; r < 14; r++) {
                unsigned v = vv[r];
                if (v != 0xFFFFFFFFu) {
                    bool in = (pass == 0) || ((v >> (shift + 10)) == prefix);
                    if (in) atomicAdd(&sm.sel.hist[(v >> shift) & 1023], 1u);
                }
            }
            __syncthreads();
            unsigned h = sm.sel.hist[tid];
            unsigned v = h;
#pragma unroll
            for (int off = 1; off < 32; off <<= 1) {
                unsigned u = __shfl_down_sync(0xffffffffu, v, off);
                if (lane + off < 32) v += u;
            }
            if (lane == 0) sm.sel.wsum[wrp] = v;
            __syncthreads();
            if (tid < 32) {
                unsigned wv = sm.sel.wsum[tid];
                unsigned acc = wv;
#pragma unroll
                for (int off = 1; off < 32; off <<= 1) {
                    unsigned u = __shfl_down_sync(0xffffffffu, acc, off);
                    if (tid + off < 32) acc += u;
                }
                sm.sel.wsum[tid] = acc - wv;
            }
            __syncthreads();
            unsigned S = v + sm.sel.wsum[wrp];
            unsigned nxt = S - h;
            if (S >= target && nxt < target) { s_B = tid; s_above = nxt; }
            __syncthreads();
            prefix = (prefix << 10) | s_B;
            target = target - s_above;
            __syncthreads();
        }
        unsigned T = prefix;

        if (tid == 0) s_cnt = 0;
        __syncthreads();
#pragma unroll
        for (int r = 0; r < 14; r++) {
            int i = tid + r * 1024;
            if (i < NANCH && vv[r] >= T && vv[r] != 0xFFFFFFFFu) {
                unsigned pos = atomicAdd(&s_cnt, 1u);
                if (pos < CAND) g_cand[b * CAND + pos] = kb[i];
            }
        }
        __syncthreads();
        if (tid == 0) g_ncand[b] = (int)min(s_cnt, (unsigned)CAND);
    }
    batch_barrier(b);

    // ================= stage 3: rank-by-count + gather (16 blocks/batch, 128 active thr) =================
    if (bl < 16) {
        int n = g_ncand[b];
        int n4 = (n + 3) & ~3;
        for (int i = tid; i < n4; i += 1024)
            sm.skey[i] = (i < n) ? g_cand[b * CAND + i] : 0ULL;
        __syncthreads();

        unsigned mu = 0;
        if (tid < 128) {
            int c = bl * 128 + tid;
            if (c < n) {
                unsigned long long k = sm.skey[c];
                int cnt = 0;
                for (int j = 0; j < n4; j += 4) {
                    cnt += (int)(sm.skey[j]     > k) + (int)(sm.skey[j + 1] > k)
                         + (int)(sm.skey[j + 2] > k) + (int)(sm.skey[j + 3] > k);
                }
                if (cnt < TOPK) {
                    unsigned sbits = (unsigned)(k >> 34);
                    int a = 16383 - (int)((k >> 7) & 16383);
                    int cl = (int)(k & 127);
                    float sc = __uint_as_float(sbits);
                    float4 bx = g_box4[b * NANCH + a];
                    int to = b * 1024 + cnt;
                    g_tsc[to] = sc;
                    g_tcl[to] = cl;
                    g_tbox[to] = bx;
                    bool valid = (sc >= 0.05f);
                    float m = valid ? fmaxf(fmaxf(bx.x, bx.y), fmaxf(bx.z, bx.w)) : 0.0f;
                    mu = enc_f(m);
                }
            }
        }
#pragma unroll
        for (int o = 16; o > 0; o >>= 1) mu = max(mu, __shfl_down_sync(0xffffffffu, mu, o));
        if (lane == 0 && wrp < 4 && mu != 0) atomicMax(&g_maxc_u[b], mu);
    }
    batch_barrier(b);

    // ================= stage 4: suppression bitmask =================
    // block bl handles rows [bl*32, bl*32+32): one row/warp; only boxes j >= bl*32 needed.
    if (bl * 32 < TOPK) {
        int base = b * 1024;
        float maxc = dec_f(g_maxc_u[b]);
        int jstart = bl * 32;
        {
            int idx = jstart + tid;
            if (idx < TOPK) {
                float4 bx = g_tbox[base + idx];
                float off = __fmul_rn((float)g_tcl[base + idx], __fadd_rn(maxc, 1.0f));
                float ox1 = __fadd_rn(bx.x, off);
                float oy1 = __fadd_rn(bx.y, off);
                float ox2 = __fadd_rn(bx.z, off);
                float oy2 = __fadd_rn(bx.w, off);
                sm.msk.sx1[idx] = ox1; sm.msk.sy1[idx] = oy1;
                sm.msk.sx2[idx] = ox2; sm.msk.sy2[idx] = oy2;
                sm.msk.sar[idx] = __fmul_rn(__fadd_rn(__fsub_rn(ox2, ox1), 1.0f),
                                            __fadd_rn(__fsub_rn(oy2, oy1), 1.0f));
            }
        }
        __syncthreads();

        int i = bl * 32 + wrp;
        if (i < TOPK) {
            float x1i = sm.msk.sx1[i], y1i = sm.msk.sy1[i];
            float x2i = sm.msk.sx2[i], y2i = sm.msk.sy2[i];
            float ai  = sm.msk.sar[i];
            unsigned* mrowp = g_mask + ((size_t)(b * TOPK + i)) * 32;

            unsigned rowor = 0;
#pragma unroll 4
            for (int w = bl; w < 32; w++) {
                int j = w * 32 + lane;
                unsigned bit = 0;
                if (j > i && j < TOPK) {
                    float xx1 = fmaxf(x1i, sm.msk.sx1[j]);
                    float yy1 = fmaxf(y1i, sm.msk.sy1[j]);
                    float xx2 = fminf(x2i, sm.msk.sx2[j]);
                    float yy2 = fminf(y2i, sm.msk.sy2[j]);
                    float iw = fmaxf(__fsub_rn(xx2, xx1), 0.0f);
                    float ih = fmaxf(__fsub_rn(yy2, yy1), 0.0f);
                    float inter = __fmul_rn(iw, ih);
                    // inter==0 -> iou in {0,-0,NaN}, never > 0.6: skip divide exactly.
                    if (inter > 0.0f) {
                        float uni = __fsub_rn(__fadd_rn(ai, sm.msk.sar[j]), inter);
                        float iou = __fdiv_rn(inter, uni);
                        bit = (iou > 0.6f) ? 1u : 0u;
                    }
                }
                unsigned word = __ballot_sync(0xffffffffu, bit);
                if (lane == 0) {
                    mrowp[w] = word;
                    rowor |= word;
                }
            }
            if (lane == 0) g_rnz[b * TOPK + i] = (rowor != 0) ? 1 : 0;
        }
    }
    batch_barrier(b);

    // ================= stage 5: greedy scan + output (leader block per batch) =================
    if (bl != 0) return;
    {
        int base = b * 1024;
        {
            int t = tid;
            int v = 0, nz = 0;
            if (t < TOPK) {
                v = (g_tsc[base + t] >= 0.05f) ? 1 : 0;
                nz = g_rnz[b * TOPK + t];
            }
            unsigned bv = __ballot_sync(0xffffffffu, v);
            unsigned bn = __ballot_sync(0xffffffffu, nz);
            if (lane == 0 && t < TOPK) { s_valid[t >> 5] = bv; s_ne[t >> 5] = bn; }
        }
        if (tid < 32) s_removed[tid] = 0;
        __syncthreads();

        if (tid < 32) {
            for (int w = 0; w < 32; ++w) {
                unsigned cand = s_valid[w] & s_ne[w];
                while (true) {
                    unsigned rm = s_removed[w];
                    unsigned act = cand & ~rm;
                    if (!act) break;
                    int bp = __ffs(act) - 1;
                    cand &= ~(1u << bp);
                    int i = w * 32 + bp;
                    unsigned mrow = g_mask[((size_t)(b * TOPK + i)) * 32 + lane];
                    s_removed[lane] = s_removed[lane] | mrow;
                    __syncwarp();
                }
            }
        }
        __syncthreads();

        float4* boxout = (float4*)(out + (size_t)2 * NB * TOPK);
        int t = tid;
        if (t < TOPK) {
            unsigned rem = s_removed[t >> 5];
            bool keep = (((s_valid[t >> 5] >> (t & 31)) & 1u) != 0u) &&
                        (((rem >> (t & 31)) & 1u) == 0u);
            int to = base + t;
            out[b * TOPK + t] = keep ? g_tsc[to] : 0.0f;
            out[NB * TOPK + b * TOPK + t] = keep ? (float)g_tcl[to] : 0.0f;
            float4 bx = g_tbox[to];
            if (!keep) bx = make_float4(0.f, 0.f, 0.f, 0.f);
            boxout[b * TOPK + t] = bx;
        }
    }
}

// ---------------- launch: one kernel, zero gaps ----------------
extern "C" void kernel_launch(void* const* d_in, const int* in_sizes, int n_in,
                              void* d_out, int out_size) {
    (void)in_sizes; (void)n_in; (void)out_size;
    Ptrs P;
    for (int i = 0; i < 5; i++) {
        P.cls[i] = (const float*)d_in[i];
        P.cnt[i] = (const float*)d_in[5 + i];
        P.reg[i] = (const float*)d_in[10 + i];
    }
    k_all<<<NBLK, 1024>>>(P, (float*)d_out);
}

// round 16
// speedup vs baseline: 1.1171x; 1.0889x over previous
#include <cuda_runtime.h>
#include <stdint.h>

#define NB 8
#define NANCH 13343
#define TOPK 1000
#define CAND 2048
#define NCLS 80

// ---------------- scratch (device globals; no allocation allowed) ----------------
__device__ unsigned long long g_key[NB * NANCH];   // score<<34 | (16383-a)<<7 | cls
__device__ unsigned           g_sbits[NB * NANCH];
__device__ float4             g_box4[NB * NANCH];

__device__ unsigned long long g_cand[NB * CAND];
__device__ int                g_ncand[NB];
__device__ unsigned           g_maxc_u[NB];        // order-preserving encoded float

__device__ float    g_tsc[NB * 1024];
__device__ int      g_tcl[NB * 1024];
__device__ float4   g_tbox[NB * 1024];

__device__ unsigned char g_keep[NB * 1024];        // zeroed each run by k_select

struct Ptrs {
    const float* cls[5];
    const float* cnt[5];
    const float* reg[5];
};

__device__ __forceinline__ unsigned enc_f(float f) {
    unsigned b = __float_as_uint(f);
    return (b & 0x80000000u) ? ~b : (b | 0x80000000u);
}
__device__ __forceinline__ float dec_f(unsigned u) {
    unsigned b = (u & 0x80000000u) ? (u ^ 0x80000000u) : ~u;
    return __uint_as_float(b);
}

// ---------------- XLA-compatible sigmoid (fma-free Horner, verified passing) ----------------
__device__ __forceinline__ float xla_tanh(float x) {
    float xc = fminf(fmaxf(x, -7.90531110763549805f), 7.90531110763549805f);
    float x2 = __fmul_rn(xc, xc);
    float p = -2.76076847742355e-16f;
    p = __fadd_rn(__fmul_rn(p, x2), 2.00018790482477e-13f);
    p = __fadd_rn(__fmul_rn(p, x2), -8.60467152213735e-11f);
    p = __fadd_rn(__fmul_rn(p, x2), 5.12229709037114e-08f);
    p = __fadd_rn(__fmul_rn(p, x2), 1.48572235717979e-05f);
    p = __fadd_rn(__fmul_rn(p, x2), 6.37261928875436e-04f);
    p = __fadd_rn(__fmul_rn(p, x2), 4.89352455891786e-03f);
    p = __fmul_rn(xc, p);
    float q = 1.19825839466702e-06f;
    q = __fadd_rn(__fmul_rn(q, x2), 1.18534705686654e-04f);
    q = __fadd_rn(__fmul_rn(q, x2), 2.26843463243900e-03f);
    q = __fadd_rn(__fmul_rn(q, x2), 4.89352518554385e-03f);
    float r = __fdiv_rn(p, q);
    return (fabsf(x) < 0.0004f) ? x : r;
}
__device__ __forceinline__ float xla_sigmoid(float x) {
    return __fadd_rn(0.5f, __fmul_rn(0.5f, xla_tanh(__fmul_rn(0.5f, x))));
}

// ---------------- kernel 1: per-anchor packed key + box (r6 form) ----------------
__global__ void k_score(Ptrs P) {
    int t = blockIdx.x * blockDim.x + threadIdx.x;
    if (t >= NB * NANCH) return;
    int b = t / NANCH;
    int a = t - b * NANCH;

    int l, p;
    if (a < 10000)      { l = 0; p = a; }
    else if (a < 12500) { l = 1; p = a - 10000; }
    else if (a < 13125) { l = 2; p = a - 12500; }
    else if (a < 13294) { l = 3; p = a - 13125; }
    else                { l = 4; p = a - 13294; }

    const int wlv[5] = {100, 50, 25, 13, 7};
    const int hwv[5] = {10000, 2500, 625, 169, 49};
    const int stv[5] = {8, 16, 32, 64, 128};
    int w = wlv[l], HW = hwv[l], s = stv[l];
    int y = p / w, x = p - y * w;
    float cx = (float)(x * s + (s >> 1));
    float cy = (float)(y * s + (s >> 1));

    const float* cls = P.cls[l];
    const float* cnt = P.cnt[l];
    const float* reg = P.reg[l];

    // argmax over sigmoid == argmax over logits (monotone); top-2 + exact
    // JAX first-occurrence semantics on their sigmoids.
    float ninf = -__int_as_float(0x7f800000);
    float m1 = ninf, m2 = ninf;
    int i1 = 0, i2 = 0;
    const float* cp = cls + (size_t)b * NCLS * HW + p;
#pragma unroll 8
    for (int c = 0; c < NCLS; c++) {
        float v = __ldg(cp + (size_t)c * HW);
        if (v > m1) { m2 = m1; i2 = i1; m1 = v; i1 = c; }
        else if (v > m2) { m2 = v; i2 = c; }
    }
    float s1 = xla_sigmoid(m1);
    float s2 = xla_sigmoid(m2);
    float best = s1;
    int bi = i1;
    if (s2 > s1 || (s2 == s1 && i2 < i1)) { best = fmaxf(s1, s2); bi = i2; }
    float cv = xla_sigmoid(__ldg(cnt + (size_t)b * HW + p));
    float score = sqrtf(__fmul_rn(best, cv));

    int o = b * NANCH + a;
    unsigned sbits = __float_as_uint(score);
    g_sbits[o] = sbits;
    g_key[o] = ((unsigned long long)sbits << 34)
             | ((unsigned long long)(16383 - a) << 7)
             | (unsigned long long)(bi + 1);

    float r0 = __ldg(reg + ((size_t)b * 4 + 0) * HW + p);
    float r1 = __ldg(reg + ((size_t)b * 4 + 1) * HW + p);
    float r2 = __ldg(reg + ((size_t)b * 4 + 2) * HW + p);
    float r3 = __ldg(reg + ((size_t)b * 4 + 3) * HW + p);
    g_box4[o] = make_float4(__fsub_rn(cx, r0), __fsub_rn(cy, r1),
                            __fadd_rn(cx, r2), __fadd_rn(cy, r3));
}

// ---------------- kernel 2: radix-select threshold + compact candidates (r6 form) ----------------
__global__ __launch_bounds__(1024) void k_select() {
    __shared__ unsigned s_hist[1024];
    __shared__ unsigned s_wsum[32];
    __shared__ unsigned s_B, s_above, s_cnt;

    int b = blockIdx.x;
    int tid = threadIdx.x;
    int lane = tid & 31, wid = tid >> 5;
    const unsigned* sb = g_sbits + b * NANCH;
    const unsigned long long* kb = g_key + b * NANCH;

    if (tid == 0) g_maxc_u[b] = enc_f(-__int_as_float(0x7f800000));
    g_keep[b * 1024 + tid] = 0;   // reset keep flags for this run

    unsigned vv[14];
#pragma unroll
    for (int r = 0; r < 14; r++) {
        int i = tid + r * 1024;
        vv[r] = (i < NANCH) ? sb[i] : 0xFFFFFFFFu;
    }

    unsigned prefix = 0;
    unsigned target = TOPK;
    for (int pass = 0; pass < 3; pass++) {
        int shift = 20 - 10 * pass;
        s_hist[tid] = 0;
        __syncthreads();
#pragma unroll
        for (int r = 0; r < 14; r++) {
            unsigned v = vv[r];
            if (v != 0xFFFFFFFFu) {
                bool in = (pass == 0) || ((v >> (shift + 10)) == prefix);
                if (in) atomicAdd(&s_hist[(v >> shift) & 1023], 1u);
            }
        }
        __syncthreads();
        unsigned h = s_hist[tid];
        unsigned v = h;
#pragma unroll
        for (int off = 1; off < 32; off <<= 1) {
            unsigned u = __shfl_down_sync(0xffffffffu, v, off);
            if (lane + off < 32) v += u;
        }
        if (lane == 0) s_wsum[wid] = v;
        __syncthreads();
        if (tid < 32) {
            unsigned wv = s_wsum[tid];
            unsigned acc = wv;
#pragma unroll
            for (int off = 1; off < 32; off <<= 1) {
                unsigned u = __shfl_down_sync(0xffffffffu, acc, off);
                if (tid + off < 32) acc += u;
            }
            s_wsum[tid] = acc - wv;
        }
        __syncthreads();
        unsigned S = v + s_wsum[wid];
        unsigned nxt = S - h;
        if (S >= target && nxt < target) { s_B = tid; s_above = nxt; }
        __syncthreads();
        prefix = (prefix << 10) | s_B;
        target = target - s_above;
        __syncthreads();
    }
    unsigned T = prefix;

    if (tid == 0) s_cnt = 0;
    __syncthreads();
#pragma unroll
    for (int r = 0; r < 14; r++) {
        int i = tid + r * 1024;
        if (i < NANCH && vv[r] >= T && vv[r] != 0xFFFFFFFFu) {
            unsigned pos = atomicAdd(&s_cnt, 1u);
            if (pos < CAND) g_cand[b * CAND + pos] = kb[i];
        }
    }
    __syncthreads();
    if (tid == 0) g_ncand[b] = (int)min(s_cnt, (unsigned)CAND);
}

// ---------------- kernel 3: rank-by-count + gather into rank order (r6 form) ----------------
__global__ __launch_bounds__(256) void k_rankgather() {
    __shared__ unsigned long long skey[CAND];
    int b = blockIdx.y;
    int s = blockIdx.x;
    int tid = threadIdx.x;
    int n = g_ncand[b];
    if (s * 256 >= n) return;
    int n4 = (n + 3) & ~3;

    for (int i = tid; i < n4; i += 256)
        skey[i] = (i < n) ? g_cand[b * CAND + i] : 0ULL;
    __syncthreads();

    int t = s * 256 + tid;
    unsigned mu = 0;
    if (t < n) {
        unsigned long long k = skey[t];
        int cnt = 0;
        for (int j = 0; j < n4; j += 4) {
            cnt += (int)(skey[j]     > k) + (int)(skey[j + 1] > k)
                 + (int)(skey[j + 2] > k) + (int)(skey[j + 3] > k);
        }
        if (cnt < TOPK) {
            unsigned sbits = (unsigned)(k >> 34);
            int a = 16383 - (int)((k >> 7) & 16383);
            int cl = (int)(k & 127);
            float sc = __uint_as_float(sbits);
            float4 bx = g_box4[b * NANCH + a];
            int to = b * 1024 + cnt;
            g_tsc[to] = sc;
            g_tcl[to] = cl;
            g_tbox[to] = bx;
            bool valid = (sc >= 0.05f);
            float m = valid ? fmaxf(fmaxf(bx.x, bx.y), fmaxf(bx.z, bx.w)) : 0.0f;
            mu = enc_f(m);
        }
    }
#pragma unroll
    for (int o = 16; o > 0; o >>= 1) mu = max(mu, __shfl_down_sync(0xffffffffu, mu, o));
    if ((tid & 31) == 0 && mu != 0) atomicMax(&g_maxc_u[b], mu);
}

// ---------------- kernel 4: per-(batch,class) NMS (one warp each) ----------------
// Cross-class pairs have inter == 0 exactly (class offsets separate boxes by >= 1
// while valid raw coords are <= maxc), so iou in {0,-0,NaN} and never > 0.6.
// Hence global greedy NMS in rank order == independent per-class greedy NMS in
// rank order. Same-class IOU uses the byte-identical rn-op sequence as before.
__global__ __launch_bounds__(32) void k_cnms() {
    __shared__ float sx1[1024], sy1[1024], sx2[1024], sy2[1024], sar[1024];
    __shared__ short slist[1024];
    __shared__ unsigned char alive[1024];

    int b = blockIdx.y;
    int cls = blockIdx.x + 1;     // classes 1..80
    int lane = threadIdx.x;
    int base = b * 1024;

    // collect this class's VALID entries in ascending rank order
    // (invalid entries never suppress — keep[i] is false — and output 0 anyway)
    int m = 0;
#pragma unroll 4
    for (int it = 0; it < 32; it++) {
        int t = it * 32 + lane;
        int match = 0;
        if (t < TOPK)
            match = (g_tcl[base + t] == cls) && (g_tsc[base + t] >= 0.05f);
        unsigned bal = __ballot_sync(0xffffffffu, match);
        if (match) {
            int pos = m + __popc(bal & ((1u << lane) - 1u));
            slist[pos] = (short)t;
        }
        m += __popc(bal);
    }
    if (m == 0) return;

    // offset coords + areas, exactly the former k_mask preamble ops
    float maxc = dec_f(g_maxc_u[b]);
    float off = __fmul_rn((float)cls, __fadd_rn(maxc, 1.0f));
    for (int j = lane; j < m; j += 32) {
        float4 bx = g_tbox[base + slist[j]];
        float ox1 = __fadd_rn(bx.x, off);
        float oy1 = __fadd_rn(bx.y, off);
        float ox2 = __fadd_rn(bx.z, off);
        float oy2 = __fadd_rn(bx.w, off);
        sx1[j] = ox1; sy1[j] = oy1; sx2[j] = ox2; sy2[j] = oy2;
        sar[j] = __fmul_rn(__fadd_rn(__fsub_rn(ox2, ox1), 1.0f),
                           __fadd_rn(__fsub_rn(oy2, oy1), 1.0f));
        alive[j] = 1;
    }
    __syncwarp();

    // greedy in rank order (== global rank order restricted to this class)
    for (int k = 0; k < m; k++) {
        if (!alive[k]) { __syncwarp(); continue; }
        float kx1 = sx1[k], ky1 = sy1[k], kx2 = sx2[k], ky2 = sy2[k], ka = sar[k];
        for (int j0 = k + 1; j0 < m; j0 += 32) {
            int j = j0 + lane;
            if (j < m) {
                float xx1 = fmaxf(kx1, sx1[j]);
                float yy1 = fmaxf(ky1, sy1[j]);
                float xx2 = fminf(kx2, sx2[j]);
                float yy2 = fminf(ky2, sy2[j]);
                float iw = fmaxf(__fsub_rn(xx2, xx1), 0.0f);
                float ih = fmaxf(__fsub_rn(yy2, yy1), 0.0f);
                float inter = __fmul_rn(iw, ih);
                if (inter > 0.0f) {   // inter==0 -> iou in {0,-0,NaN}, never > 0.6
                    float uni = __fsub_rn(__fadd_rn(ka, sar[j]), inter);
                    float iou = __fdiv_rn(inter, uni);
                    if (iou > 0.6f) alive[j] = 0;
                }
            }
        }
        __syncwarp();
    }

    // publish keep flags
    for (int j = lane; j < m; j += 32)
        if (alive[j]) g_keep[base + slist[j]] = 1;
}

// ---------------- kernel 5: output writer ----------------
__global__ __launch_bounds__(256) void k_out(float* out) {
    int b = blockIdx.x;
    int tid = threadIdx.x;
    int base = b * 1024;
    float4* boxout = (float4*)(out + (size_t)2 * NB * TOPK);
    for (int k = 0; k < 4; k++) {
        int t = k * 256 + tid;
        if (t < TOPK) {
            bool keep = (g_keep[base + t] != 0);
            int to = base + t;
            out[b * TOPK + t] = keep ? g_tsc[to] : 0.0f;
            out[NB * TOPK + b * TOPK + t] = keep ? (float)g_tcl[to] : 0.0f;
            float4 bx = g_tbox[to];
            if (!keep) bx = make_float4(0.f, 0.f, 0.f, 0.f);
            boxout[b * TOPK + t] = bx;
        }
    }
}

// ---------------- launch ----------------
extern "C" void kernel_launch(void* const* d_in, const int* in_sizes, int n_in,
                              void* d_out, int out_size) {
    (void)in_sizes; (void)n_in; (void)out_size;
    Ptrs P;
    for (int i = 0; i < 5; i++) {
        P.cls[i] = (const float*)d_in[i];
        P.cnt[i] = (const float*)d_in[5 + i];
        P.reg[i] = (const float*)d_in[10 + i];
    }
    int total = NB * NANCH;
    k_score<<<(total + 255) / 256, 256>>>(P);
    k_select<<<NB, 1024>>>();
    dim3 rg(CAND / 256, NB);
    k_rankgather<<<rg, 256>>>();
    dim3 cg(NCLS, NB);
    k_cnms<<<cg, 32>>>();
    k_out<<<NB, 256>>>((float*)d_out);
}

// round 17
// speedup vs baseline: 1.1618x; 1.0400x over previous
#include <cuda_runtime.h>
#include <stdint.h>

#define NB 8
#define NANCH 13343
#define TOPK 1000
#define CAND 2048
#define NCLS 80

// ---------------- scratch (device globals; no allocation allowed) ----------------
__device__ unsigned long long g_key[NB * NANCH];   // score<<34 | (16383-a)<<7 | cls
__device__ unsigned           g_sbits[NB * NANCH];
__device__ float4             g_box4[NB * NANCH];

__device__ unsigned long long g_cand[NB * CAND];
__device__ int                g_ncand[NB];
__device__ unsigned           g_maxc_u[NB];        // order-preserving encoded float

__device__ float    g_tsc[NB * 1024];
__device__ int      g_tcl[NB * 1024];
__device__ float4   g_tbox[NB * 1024];

__device__ unsigned char g_keep[NB * 1024];        // zeroed each run by k_select

struct Ptrs {
    const float* cls[5];
    const float* cnt[5];
    const float* reg[5];
};

__device__ __forceinline__ unsigned enc_f(float f) {
    unsigned b = __float_as_uint(f);
    return (b & 0x80000000u) ? ~b : (b | 0x80000000u);
}
__device__ __forceinline__ float dec_f(unsigned u) {
    unsigned b = (u & 0x80000000u) ? (u ^ 0x80000000u) : ~u;
    return __uint_as_float(b);
}

// ---------------- XLA-compatible sigmoid (fma-free Horner, verified passing) ----------------
__device__ __forceinline__ float xla_tanh(float x) {
    float xc = fminf(fmaxf(x, -7.90531110763549805f), 7.90531110763549805f);
    float x2 = __fmul_rn(xc, xc);
    float p = -2.76076847742355e-16f;
    p = __fadd_rn(__fmul_rn(p, x2), 2.00018790482477e-13f);
    p = __fadd_rn(__fmul_rn(p, x2), -8.60467152213735e-11f);
    p = __fadd_rn(__fmul_rn(p, x2), 5.12229709037114e-08f);
    p = __fadd_rn(__fmul_rn(p, x2), 1.48572235717979e-05f);
    p = __fadd_rn(__fmul_rn(p, x2), 6.37261928875436e-04f);
    p = __fadd_rn(__fmul_rn(p, x2), 4.89352455891786e-03f);
    p = __fmul_rn(xc, p);
    float q = 1.19825839466702e-06f;
    q = __fadd_rn(__fmul_rn(q, x2), 1.18534705686654e-04f);
    q = __fadd_rn(__fmul_rn(q, x2), 2.26843463243900e-03f);
    q = __fadd_rn(__fmul_rn(q, x2), 4.89352518554385e-03f);
    float r = __fdiv_rn(p, q);
    return (fabsf(x) < 0.0004f) ? x : r;
}
__device__ __forceinline__ float xla_sigmoid(float x) {
    return __fadd_rn(0.5f, __fmul_rn(0.5f, xla_tanh(__fmul_rn(0.5f, x))));
}

// ---------------- kernel 1: per-anchor packed key + box (r6 form) ----------------
__global__ void k_score(Ptrs P) {
    int t = blockIdx.x * blockDim.x + threadIdx.x;
    if (t >= NB * NANCH) return;
    int b = t / NANCH;
    int a = t - b * NANCH;

    int l, p;
    if (a < 10000)      { l = 0; p = a; }
    else if (a < 12500) { l = 1; p = a - 10000; }
    else if (a < 13125) { l = 2; p = a - 12500; }
    else if (a < 13294) { l = 3; p = a - 13125; }
    else                { l = 4; p = a - 13294; }

    const int wlv[5] = {100, 50, 25, 13, 7};
    const int hwv[5] = {10000, 2500, 625, 169, 49};
    const int stv[5] = {8, 16, 32, 64, 128};
    int w = wlv[l], HW = hwv[l], s = stv[l];
    int y = p / w, x = p - y * w;
    float cx = (float)(x * s + (s >> 1));
    float cy = (float)(y * s + (s >> 1));

    const float* cls = P.cls[l];
    const float* cnt = P.cnt[l];
    const float* reg = P.reg[l];

    // argmax over sigmoid == argmax over logits (monotone); top-2 + exact
    // JAX first-occurrence semantics on their sigmoids.
    float ninf = -__int_as_float(0x7f800000);
    float m1 = ninf, m2 = ninf;
    int i1 = 0, i2 = 0;
    const float* cp = cls + (size_t)b * NCLS * HW + p;
#pragma unroll 8
    for (int c = 0; c < NCLS; c++) {
        float v = __ldg(cp + (size_t)c * HW);
        if (v > m1) { m2 = m1; i2 = i1; m1 = v; i1 = c; }
        else if (v > m2) { m2 = v; i2 = c; }
    }
    float s1 = xla_sigmoid(m1);
    float s2 = xla_sigmoid(m2);
    float best = s1;
    int bi = i1;
    if (s2 > s1 || (s2 == s1 && i2 < i1)) { best = fmaxf(s1, s2); bi = i2; }
    float cv = xla_sigmoid(__ldg(cnt + (size_t)b * HW + p));
    float score = sqrtf(__fmul_rn(best, cv));

    int o = b * NANCH + a;
    unsigned sbits = __float_as_uint(score);
    g_sbits[o] = sbits;
    g_key[o] = ((unsigned long long)sbits << 34)
             | ((unsigned long long)(16383 - a) << 7)
             | (unsigned long long)(bi + 1);

    float r0 = __ldg(reg + ((size_t)b * 4 + 0) * HW + p);
    float r1 = __ldg(reg + ((size_t)b * 4 + 1) * HW + p);
    float r2 = __ldg(reg + ((size_t)b * 4 + 2) * HW + p);
    float r3 = __ldg(reg + ((size_t)b * 4 + 3) * HW + p);
    g_box4[o] = make_float4(__fsub_rn(cx, r0), __fsub_rn(cy, r1),
                            __fadd_rn(cx, r2), __fadd_rn(cy, r3));
}

// ---------------- kernel 2: radix-select threshold + compact candidates (r6 form) ----------------
__global__ __launch_bounds__(1024) void k_select() {
    __shared__ unsigned s_hist[1024];
    __shared__ unsigned s_wsum[32];
    __shared__ unsigned s_B, s_above, s_cnt;

    int b = blockIdx.x;
    int tid = threadIdx.x;
    int lane = tid & 31, wid = tid >> 5;
    const unsigned* sb = g_sbits + b * NANCH;
    const unsigned long long* kb = g_key + b * NANCH;

    if (tid == 0) g_maxc_u[b] = enc_f(-__int_as_float(0x7f800000));
    g_keep[b * 1024 + tid] = 0;   // reset keep flags for this run

    unsigned vv[14];
#pragma unroll
    for (int r = 0; r < 14; r++) {
        int i = tid + r * 1024;
        vv[r] = (i < NANCH) ? sb[i] : 0xFFFFFFFFu;
    }

    unsigned prefix = 0;
    unsigned target = TOPK;
    for (int pass = 0; pass < 3; pass++) {
        int shift = 20 - 10 * pass;
        s_hist[tid] = 0;
        __syncthreads();
#pragma unroll
        for (int r = 0; r < 14; r++) {
            unsigned v = vv[r];
            if (v != 0xFFFFFFFFu) {
                bool in = (pass == 0) || ((v >> (shift + 10)) == prefix);
                if (in) atomicAdd(&s_hist[(v >> shift) & 1023], 1u);
            }
        }
        __syncthreads();
        unsigned h = s_hist[tid];
        unsigned v = h;
#pragma unroll
        for (int off = 1; off < 32; off <<= 1) {
            unsigned u = __shfl_down_sync(0xffffffffu, v, off);
            if (lane + off < 32) v += u;
        }
        if (lane == 0) s_wsum[wid] = v;
        __syncthreads();
        if (tid < 32) {
            unsigned wv = s_wsum[tid];
            unsigned acc = wv;
#pragma unroll
            for (int off = 1; off < 32; off <<= 1) {
                unsigned u = __shfl_down_sync(0xffffffffu, acc, off);
                if (tid + off < 32) acc += u;
            }
            s_wsum[tid] = acc - wv;
        }
        __syncthreads();
        unsigned S = v + s_wsum[wid];
        unsigned nxt = S - h;
        if (S >= target && nxt < target) { s_B = tid; s_above = nxt; }
        __syncthreads();
        prefix = (prefix << 10) | s_B;
        target = target - s_above;
        __syncthreads();
    }
    unsigned T = prefix;

    if (tid == 0) s_cnt = 0;
    __syncthreads();
#pragma unroll
    for (int r = 0; r < 14; r++) {
        int i = tid + r * 1024;
        if (i < NANCH && vv[r] >= T && vv[r] != 0xFFFFFFFFu) {
            unsigned pos = atomicAdd(&s_cnt, 1u);
            if (pos < CAND) g_cand[b * CAND + pos] = kb[i];
        }
    }
    __syncthreads();
    if (tid == 0) g_ncand[b] = (int)min(s_cnt, (unsigned)CAND);
}

// ---------------- kernel 3: rank-by-count + gather into rank order (r6 form) ----------------
__global__ __launch_bounds__(256) void k_rankgather() {
    __shared__ unsigned long long skey[CAND];
    int b = blockIdx.y;
    int s = blockIdx.x;
    int tid = threadIdx.x;
    int n = g_ncand[b];
    if (s * 256 >= n) return;
    int n4 = (n + 3) & ~3;

    for (int i = tid; i < n4; i += 256)
        skey[i] = (i < n) ? g_cand[b * CAND + i] : 0ULL;
    __syncthreads();

    int t = s * 256 + tid;
    unsigned mu = 0;
    if (t < n) {
        unsigned long long k = skey[t];
        int cnt = 0;
        for (int j = 0; j < n4; j += 4) {
            cnt += (int)(skey[j]     > k) + (int)(skey[j + 1] > k)
                 + (int)(skey[j + 2] > k) + (int)(skey[j + 3] > k);
        }
        if (cnt < TOPK) {
            unsigned sbits = (unsigned)(k >> 34);
            int a = 16383 - (int)((k >> 7) & 16383);
            int cl = (int)(k & 127);
            float sc = __uint_as_float(sbits);
            float4 bx = g_box4[b * NANCH + a];
            int to = b * 1024 + cnt;
            g_tsc[to] = sc;
            g_tcl[to] = cl;
            g_tbox[to] = bx;
            bool valid = (sc >= 0.05f);
            float m = valid ? fmaxf(fmaxf(bx.x, bx.y), fmaxf(bx.z, bx.w)) : 0.0f;
            mu = enc_f(m);
        }
    }
#pragma unroll
    for (int o = 16; o > 0; o >>= 1) mu = max(mu, __shfl_down_sync(0xffffffffu, mu, o));
    if ((tid & 31) == 0 && mu != 0) atomicMax(&g_maxc_u[b], mu);
}

// ---------------- kernel 4: per-(batch,class) NMS — 128-thread collect, warp-0 greedy ----------------
// Cross-class pairs have inter == 0 exactly (class offsets separate boxes by >= 1
// while valid raw coords are <= maxc), so iou in {0,-0,NaN} and never > 0.6.
// Hence global greedy NMS in rank order == per-class greedy in rank order.
// Collection order: chunk-major, warp-major, lane-major == ascending rank t,
// identical to the r16 sequence. All FP ops byte-identical.
__global__ __launch_bounds__(128) void k_cnms() {
    __shared__ float sx1[1024], sy1[1024], sx2[1024], sy2[1024], sar[1024];
    __shared__ short slist[1024];
    __shared__ unsigned char alive[1024];
    __shared__ unsigned s_wcnt[4];

    int b = blockIdx.y;
    int cls = blockIdx.x + 1;     // classes 1..80
    int tid = threadIdx.x;
    int lane = tid & 31, wrp = tid >> 5;
    int base = b * 1024;

    // collect this class's VALID entries in ascending rank order (parallel)
    int m = 0;
#pragma unroll 2
    for (int it = 0; it < 8; it++) {
        int t = it * 128 + tid;
        int match = 0;
        if (t < TOPK)
            match = (g_tcl[base + t] == cls) && (g_tsc[base + t] >= 0.05f);
        unsigned bal = __ballot_sync(0xffffffffu, match);
        if (lane == 0) s_wcnt[wrp] = __popc(bal);
        __syncthreads();
        int woff = 0;
#pragma unroll
        for (int w = 0; w < 4; w++)
            if (w < wrp) woff += (int)s_wcnt[w];
        if (match) {
            int pos = m + woff + __popc(bal & ((1u << lane) - 1u));
            slist[pos] = (short)t;
        }
        m += (int)(s_wcnt[0] + s_wcnt[1] + s_wcnt[2] + s_wcnt[3]);
        __syncthreads();   // protect s_wcnt reuse next iteration
    }
    if (m == 0) return;    // uniform across block

    // offset coords + areas (parallel, exact former k_mask preamble ops)
    float maxc = dec_f(g_maxc_u[b]);
    float off = __fmul_rn((float)cls, __fadd_rn(maxc, 1.0f));
    for (int j = tid; j < m; j += 128) {
        float4 bx = g_tbox[base + slist[j]];
        float ox1 = __fadd_rn(bx.x, off);
        float oy1 = __fadd_rn(bx.y, off);
        float ox2 = __fadd_rn(bx.z, off);
        float oy2 = __fadd_rn(bx.w, off);
        sx1[j] = ox1; sy1[j] = oy1; sx2[j] = ox2; sy2[j] = oy2;
        sar[j] = __fmul_rn(__fadd_rn(__fsub_rn(ox2, ox1), 1.0f),
                           __fadd_rn(__fsub_rn(oy2, oy1), 1.0f));
        alive[j] = 1;
    }
    __syncthreads();

    // greedy in rank order (warp 0; m is tiny, ~12)
    if (wrp == 0) {
        for (int k = 0; k < m; k++) {
            if (!alive[k]) { __syncwarp(); continue; }
            float kx1 = sx1[k], ky1 = sy1[k], kx2 = sx2[k], ky2 = sy2[k], ka = sar[k];
            for (int j0 = k + 1; j0 < m; j0 += 32) {
                int j = j0 + lane;
                if (j < m) {
                    float xx1 = fmaxf(kx1, sx1[j]);
                    float yy1 = fmaxf(ky1, sy1[j]);
                    float xx2 = fminf(kx2, sx2[j]);
                    float yy2 = fminf(ky2, sy2[j]);
                    float iw = fmaxf(__fsub_rn(xx2, xx1), 0.0f);
                    float ih = fmaxf(__fsub_rn(yy2, yy1), 0.0f);
                    float inter = __fmul_rn(iw, ih);
                    if (inter > 0.0f) {   // inter==0 -> iou in {0,-0,NaN}, never > 0.6
                        float uni = __fsub_rn(__fadd_rn(ka, sar[j]), inter);
                        float iou = __fdiv_rn(inter, uni);
                        if (iou > 0.6f) alive[j] = 0;
                    }
                }
            }
            __syncwarp();
        }
    }
    __syncthreads();

    // publish keep flags (parallel)
    for (int j = tid; j < m; j += 128)
        if (alive[j]) g_keep[base + slist[j]] = 1;
}

// ---------------- kernel 5: output writer ----------------
__global__ __launch_bounds__(256) void k_out(float* out) {
    int b = blockIdx.x;
    int tid = threadIdx.x;
    int base = b * 1024;
    float4* boxout = (float4*)(out + (size_t)2 * NB * TOPK);
    for (int k = 0; k < 4; k++) {
        int t = k * 256 + tid;
        if (t < TOPK) {
            bool keep = (g_keep[base + t] != 0);
            int to = base + t;
            out[b * TOPK + t] = keep ? g_tsc[to] : 0.0f;
            out[NB * TOPK + b * TOPK + t] = keep ? (float)g_tcl[to] : 0.0f;
            float4 bx = g_tbox[to];
            if (!keep) bx = make_float4(0.f, 0.f, 0.f, 0.f);
            boxout[b * TOPK + t] = bx;
        }
    }
}

// ---------------- launch ----------------
extern "C" void kernel_launch(void* const* d_in, const int* in_sizes, int n_in,
                              void* d_out, int out_size) {
    (void)in_sizes; (void)n_in; (void)out_size;
    Ptrs P;
    for (int i = 0; i < 5; i++) {
        P.cls[i] = (const float*)d_in[i];
        P.cnt[i] = (const float*)d_in[5 + i];
        P.reg[i] = (const float*)d_in[10 + i];
    }
    int total = NB * NANCH;
    k_score<<<(total + 255) / 256, 256>>>(P);
    k_select<<<NB, 1024>>>();
    dim3 rg(CAND / 256, NB);
    k_rankgather<<<rg, 256>>>();
    dim3 cg(NCLS, NB);
    k_cnms<<<cg, 128>>>();
    k_out<<<NB, 256>>>((float*)d_out);
}